// round 2
// baseline (speedup 1.0000x reference)
#include <cuda_runtime.h>
#include <cuda_bf16.h>

// ---------------------------------------------------------------------------
// VQC: 4 qubits, 3 layers, BATCH=524288.  Single fused kernel:
//  Phase A (per block, smem builder): propagate the 16 basis columns through
//     the 3 entangling layers -> 16x16 complex unitary U. Last-layer RZ is
//     dropped (diagonal phase, invisible under |amp|^2).
//  Phase B (grid-stride main loop): per thread, TWO batch elements packed in
//     the lanes of fma.rn.f32x2. Product state p = m (x) n from sincos(x/2),
//     amp = U p (512 packed FMA / 2 elems), probs, Walsh butterfly -> 4 Z's.
// ---------------------------------------------------------------------------

#define DIM 16
#define TPB 256
#define GRID 444   // 3 CTAs/SM * 148 SMs = one exact wave

// ---------------- packed f32x2 helpers (PTX-only on Blackwell) -------------
__device__ __forceinline__ unsigned long long pack2(float lo, float hi) {
    unsigned long long r;
    asm("mov.b64 %0, {%1, %2};" : "=l"(r) : "f"(lo), "f"(hi));
    return r;
}
__device__ __forceinline__ void unpack2(unsigned long long v, float& lo, float& hi) {
    asm("mov.b64 {%0, %1}, %2;" : "=f"(lo), "=f"(hi) : "l"(v));
}
__device__ __forceinline__ unsigned long long fma2(unsigned long long a,
                                                   unsigned long long b,
                                                   unsigned long long c) {
    unsigned long long d;
    asm("fma.rn.f32x2 %0, %1, %2, %3;" : "=l"(d) : "l"(a), "l"(b), "l"(c));
    return d;
}
__device__ __forceinline__ unsigned long long mul2(unsigned long long a,
                                                   unsigned long long b) {
    unsigned long long d;
    asm("mul.rn.f32x2 %0, %1, %2;" : "=l"(d) : "l"(a), "l"(b));
    return d;
}
__device__ __forceinline__ unsigned long long add2(unsigned long long a,
                                                   unsigned long long b) {
    unsigned long long d;
    asm("add.rn.f32x2 %0, %1, %2;" : "=l"(d) : "l"(a), "l"(b));
    return d;
}
__device__ __forceinline__ unsigned long long sub2(unsigned long long a,
                                                   unsigned long long b) {
    unsigned long long d;
    asm("sub.rn.f32x2 %0, %1, %2;" : "=l"(d) : "l"(a), "l"(b));
    return d;
}

// CNOT ring permutation for one layer (compile-time composable).
// Reference: state = state[:, P_i] for i = 0..3, so Q = P0(P1(P2(P3(idx)))).
__device__ __forceinline__ int cnot_q(int idx) {
    int q = idx;
#pragma unroll
    for (int i = 3; i >= 0; --i)
        q = q ^ ((((q >> (3 - i)) & 1)) << (3 - ((i + 1) & 3)));
    return q;
}

__global__ __launch_bounds__(TPB, 3)
void vqc_fused_kernel(const float* __restrict__ x, const float* __restrict__ w,
                      float* __restrict__ out, int B) {
    // smem: builder state (16 cols x 16 amps, padded stride 17 vs conflicts),
    //       gate params, and the final lane-duplicated U.
    __shared__ float2 sState[DIM * 17];
    __shared__ float4 sGate[12];
    __shared__ float4 sUd[256];   // [k*16+j] = (re,re,im,im) of U[k][j]

    const int t = threadIdx.x;

    // ---------------- Phase A: build U cooperatively ----------------------
    // gate params: thread g<12 computes (cy,sy,cz,sz) for (layer,wire)=g
    if (t < 12) {
        float cy, sy, cz, sz;
        __sincosf(0.5f * w[t * 2 + 0], &sy, &cy);
        __sincosf(0.5f * w[t * 2 + 1], &sz, &cz);
        sGate[t] = make_float4(cy, sy, cz, sz);
    }
    // init: columns of identity. entry e: col=e>>4, amp=e&15
    {
        const int col = t >> 4, amp = t & 15;
        sState[col * 17 + amp] = make_float2((amp == col) ? 1.0f : 0.0f, 0.0f);
    }
    __syncthreads();

#pragma unroll
    for (int layer = 0; layer < 3; ++layer) {
        // CNOT-ring permutation stage: new[col][idx] = old[col][Q(idx)]
        {
            const int col = t >> 4, idx = t & 15;
            const float2 v = sState[col * 17 + cnot_q(idx)];
            __syncthreads();
            sState[col * 17 + idx] = v;
            __syncthreads();
        }
        // 4 wire gates: RY then RZ (RZ dropped on the final layer — pure phase)
#pragma unroll
        for (int g = 0; g < 4; ++g) {
            if (t < 128) {
                const int bit = 3 - g;
                const int mask = 1 << bit;
                const int col = t >> 3, pair = t & 7;
                const int i0 = ((pair >> bit) << (bit + 1)) | (pair & (mask - 1));
                const int i1 = i0 | mask;
                const float4 gp = sGate[layer * 4 + g];
                const float cy = gp.x, sy = gp.y;
                const float2 a0 = sState[col * 17 + i0];
                const float2 a1 = sState[col * 17 + i1];
                // RY
                float b0r = cy * a0.x - sy * a1.x, b0i = cy * a0.y - sy * a1.y;
                float b1r = sy * a0.x + cy * a1.x, b1i = sy * a0.y + cy * a1.y;
                if (layer != 2) {
                    // RZ: bit0 amp *= (cz - i sz); bit1 amp *= (cz + i sz)
                    const float cz = gp.z, sz = gp.w;
                    const float o0r = cz * b0r + sz * b0i, o0i = cz * b0i - sz * b0r;
                    const float o1r = cz * b1r - sz * b1i, o1i = cz * b1i + sz * b1r;
                    b0r = o0r; b0i = o0i; b1r = o1r; b1i = o1i;
                }
                sState[col * 17 + i0] = make_float2(b0r, b0i);
                sState[col * 17 + i1] = make_float2(b1r, b1i);
            }
            __syncthreads();
        }
    }
    // layout stage: sUd[k*16+j] = (re,re,im,im) of column j amplitude k
    {
        const int k = t >> 4, j = t & 15;
        const float2 f = sState[j * 17 + k];
        sUd[t] = make_float4(f.x, f.x, f.y, f.y);
    }
    __syncthreads();

    // ---------------- Phase B: grid-stride batched apply -------------------
    const int numTiles = (B + 2 * TPB - 1) / (2 * TPB);
    for (int tile = blockIdx.x; tile < numTiles; tile += gridDim.x) {
        const int b0 = tile * (2 * TPB) + t;
        const int b1 = b0 + TPB;
        const bool v0 = (b0 < B), v1 = (b1 < B);

        const float4 xa = v0 ? reinterpret_cast<const float4*>(x)[b0]
                             : make_float4(0.f, 0.f, 0.f, 0.f);
        const float4 xb = v1 ? reinterpret_cast<const float4*>(x)[b1]
                             : make_float4(0.f, 0.f, 0.f, 0.f);

        float c0a, s0a, c1a, s1a, c2a, s2a, c3a, s3a;
        __sincosf(0.5f * xa.x, &s0a, &c0a);
        __sincosf(0.5f * xa.y, &s1a, &c1a);
        __sincosf(0.5f * xa.z, &s2a, &c2a);
        __sincosf(0.5f * xa.w, &s3a, &c3a);
        float c0b, s0b, c1b, s1b, c2b, s2b, c3b, s3b;
        __sincosf(0.5f * xb.x, &s0b, &c0b);
        __sincosf(0.5f * xb.y, &s1b, &c1b);
        __sincosf(0.5f * xb.z, &s2b, &c2b);
        __sincosf(0.5f * xb.w, &s3b, &c3b);

        // product state p_j, j = (b0b1)(b2b3); lanes = (elem0, elem1)
        unsigned long long pm[4], pn[4], pp[16];
        pm[0] = pack2(c0a * c1a, c0b * c1b);
        pm[1] = pack2(c0a * s1a, c0b * s1b);
        pm[2] = pack2(s0a * c1a, s0b * c1b);
        pm[3] = pack2(s0a * s1a, s0b * s1b);
        pn[0] = pack2(c2a * c3a, c2b * c3b);
        pn[1] = pack2(c2a * s3a, c2b * s3b);
        pn[2] = pack2(s2a * c3a, s2b * c3b);
        pn[3] = pack2(s2a * s3a, s2b * s3b);
#pragma unroll
        for (int a = 0; a < 4; ++a)
#pragma unroll
            for (int c = 0; c < 4; ++c)
                pp[a * 4 + c] = mul2(pm[a], pn[c]);

        // amp_k = sum_j U[k][j] * p_j ; probs via packed squares; Walsh partials
        unsigned long long prEven = 0ull, z3p = 0ull;
        unsigned long long tArr[8];
#pragma unroll
        for (int k = 0; k < DIM; ++k) {
            unsigned long long aR = 0ull, aI = 0ull;
#pragma unroll
            for (int j = 0; j < DIM; ++j) {
                const ulonglong2 u =
                    reinterpret_cast<const ulonglong2*>(sUd)[k * 16 + j];
                aR = fma2(u.x, pp[j], aR);
                aI = fma2(u.y, pp[j], aI);
            }
            const unsigned long long pr = fma2(aI, aI, mul2(aR, aR));
            if ((k & 1) == 0) {
                prEven = pr;
            } else {
                tArr[k >> 1] = add2(prEven, pr);          // level-1 sums
                z3p = add2(z3p, sub2(prEven, pr));        // qubit-3 (bit0 sign)
            }
        }
        // remaining Walsh levels
        const unsigned long long tt0 = add2(tArr[0], tArr[1]);
        const unsigned long long td0 = sub2(tArr[0], tArr[1]);
        const unsigned long long tt1 = add2(tArr[2], tArr[3]);
        const unsigned long long td1 = sub2(tArr[2], tArr[3]);
        const unsigned long long tt2 = add2(tArr[4], tArr[5]);
        const unsigned long long td2 = sub2(tArr[4], tArr[5]);
        const unsigned long long tt3 = add2(tArr[6], tArr[7]);
        const unsigned long long td3 = sub2(tArr[6], tArr[7]);
        const unsigned long long z2p = add2(add2(td0, td1), add2(td2, td3));
        const unsigned long long ttt0 = add2(tt0, tt1);
        const unsigned long long ttd0 = sub2(tt0, tt1);
        const unsigned long long ttt1 = add2(tt2, tt3);
        const unsigned long long ttd1 = sub2(tt2, tt3);
        const unsigned long long z1p = add2(ttd0, ttd1);
        const unsigned long long z0p = sub2(ttt0, ttt1);

        float z0lo, z0hi, z1lo, z1hi, z2lo, z2hi, z3lo, z3hi;
        unpack2(z0p, z0lo, z0hi);
        unpack2(z1p, z1lo, z1hi);
        unpack2(z2p, z2lo, z2hi);
        unpack2(z3p, z3lo, z3hi);
        if (v0) reinterpret_cast<float4*>(out)[b0] =
            make_float4(z0lo, z1lo, z2lo, z3lo);
        if (v1) reinterpret_cast<float4*>(out)[b1] =
            make_float4(z0hi, z1hi, z2hi, z3hi);
    }
}

// ---------------------------------------------------------------------------
extern "C" void kernel_launch(void* const* d_in, const int* in_sizes, int n_in,
                              void* d_out, int out_size) {
    // x: B*4 floats, weights: 24 floats (order-robust)
    int ix = 0, iw = 1;
    if (n_in >= 2 && in_sizes[0] <= in_sizes[1]) { ix = 1; iw = 0; }
    const float* x = (const float*)d_in[ix];
    const float* w = (const float*)d_in[iw];
    float* out = (float*)d_out;
    const int B = in_sizes[ix] / 4;

    vqc_fused_kernel<<<GRID, TPB>>>(x, w, out, B);
}

// round 3
// speedup vs baseline: 1.5656x; 1.5656x over previous
#include <cuda_runtime.h>
#include <cuda_bf16.h>

// ---------------------------------------------------------------------------
// VQC: 4 qubits, 3 layers, BATCH=524288. Single fused kernel.
//  Phase A: per-block smem builder -> 16x16 complex unitary U of the 3
//           entangling layers (last-layer RZ dropped: pure phase).
//  Phase B: each thread processes 4 batch elements. Lanes of fma.rn.f32x2 are
//           ADJACENT j-COLUMNS of one element: u=(U[k][2j],U[k][2j+1]),
//           pp=(p_2j,p_2j+1). One LDS.128 = 4 distinct U scalars, reused by
//           4 elements => 32 LDS.128/elem (R1 was 64, R2 was 128).
// ---------------------------------------------------------------------------

#define DIM 16
#define TPB 256
#define EPT 4

// ---------------- packed f32x2 helpers (PTX-only on Blackwell) -------------
__device__ __forceinline__ unsigned long long pack2(float lo, float hi) {
    unsigned long long r;
    asm("mov.b64 %0, {%1, %2};" : "=l"(r) : "f"(lo), "f"(hi));
    return r;
}
__device__ __forceinline__ void unpack2(unsigned long long v, float& lo, float& hi) {
    asm("mov.b64 {%0, %1}, %2;" : "=f"(lo), "=f"(hi) : "l"(v));
}
__device__ __forceinline__ unsigned long long fma2(unsigned long long a,
                                                   unsigned long long b,
                                                   unsigned long long c) {
    unsigned long long d;
    asm("fma.rn.f32x2 %0, %1, %2, %3;" : "=l"(d) : "l"(a), "l"(b), "l"(c));
    return d;
}
__device__ __forceinline__ unsigned long long mul2(unsigned long long a,
                                                   unsigned long long b) {
    unsigned long long d;
    asm("mul.rn.f32x2 %0, %1, %2;" : "=l"(d) : "l"(a), "l"(b));
    return d;
}

// CNOT ring permutation for one layer (gather index).
__device__ __forceinline__ int cnot_q(int idx) {
    int q = idx;
#pragma unroll
    for (int i = 3; i >= 0; --i)
        q = q ^ ((((q >> (3 - i)) & 1)) << (3 - ((i + 1) & 3)));
    return q;
}

__global__ __launch_bounds__(TPB, 2)
void vqc_fused_kernel(const float* __restrict__ x, const float* __restrict__ w,
                      float* __restrict__ out, int B) {
    __shared__ float2 sState[DIM * 17];
    __shared__ float4 sGate[12];
    // sU[k][c]: c=0..3 -> re[k][4c..4c+3], c=4..7 -> im[k][4(c-4)..]
    __shared__ ulonglong2 sU[DIM][8];

    const int t = threadIdx.x;

    // ---------------- Phase A: build U cooperatively ----------------------
    if (t < 12) {
        float cy, sy, cz, sz;
        __sincosf(0.5f * w[t * 2 + 0], &sy, &cy);
        __sincosf(0.5f * w[t * 2 + 1], &sz, &cz);
        sGate[t] = make_float4(cy, sy, cz, sz);
    }
    {
        const int col = t >> 4, amp = t & 15;
        sState[col * 17 + amp] = make_float2((amp == col) ? 1.0f : 0.0f, 0.0f);
    }
    __syncthreads();

#pragma unroll
    for (int layer = 0; layer < 3; ++layer) {
        {   // CNOT ring stage
            const int col = t >> 4, idx = t & 15;
            const float2 v = sState[col * 17 + cnot_q(idx)];
            __syncthreads();
            sState[col * 17 + idx] = v;
            __syncthreads();
        }
#pragma unroll
        for (int g = 0; g < 4; ++g) {
            if (t < 128) {
                const int bit = 3 - g;
                const int mask = 1 << bit;
                const int col = t >> 3, pair = t & 7;
                const int i0 = ((pair >> bit) << (bit + 1)) | (pair & (mask - 1));
                const int i1 = i0 | mask;
                const float4 gp = sGate[layer * 4 + g];
                const float cy = gp.x, sy = gp.y;
                const float2 a0 = sState[col * 17 + i0];
                const float2 a1 = sState[col * 17 + i1];
                float b0r = cy * a0.x - sy * a1.x, b0i = cy * a0.y - sy * a1.y;
                float b1r = sy * a0.x + cy * a1.x, b1i = sy * a0.y + cy * a1.y;
                if (layer != 2) {   // RZ (dropped on last layer: pure phase)
                    const float cz = gp.z, sz = gp.w;
                    const float o0r = cz * b0r + sz * b0i, o0i = cz * b0i - sz * b0r;
                    const float o1r = cz * b1r - sz * b1i, o1i = cz * b1i + sz * b1r;
                    b0r = o0r; b0i = o0i; b1r = o1r; b1i = o1i;
                }
                sState[col * 17 + i0] = make_float2(b0r, b0i);
                sState[col * 17 + i1] = make_float2(b1r, b1i);
            }
            __syncthreads();
        }
    }
    {   // layout: row k = [re x16 | im x16] floats
        const int k = t >> 4, j = t & 15;
        const float2 f = sState[j * 17 + k];
        float* fU = reinterpret_cast<float*>(sU);
        fU[k * 32 + j]      = f.x;
        fU[k * 32 + 16 + j] = f.y;
    }
    __syncthreads();

    // ---------------- Phase B: 4 elements per thread -----------------------
    const int base = blockIdx.x * (TPB * EPT) + t;
    bool valid[EPT];
    unsigned long long pp[EPT][8];   // (p_2j, p_2j+1)

#pragma unroll
    for (int e = 0; e < EPT; ++e) {
        const int b = base + e * TPB;
        valid[e] = (b < B);
        const float4 xv = valid[e] ? reinterpret_cast<const float4*>(x)[b]
                                   : make_float4(0.f, 0.f, 0.f, 0.f);
        float c0, s0, c1, s1, c2, s2, c3, s3;
        __sincosf(0.5f * xv.x, &s0, &c0);
        __sincosf(0.5f * xv.y, &s1, &c1);
        __sincosf(0.5f * xv.z, &s2, &c2);
        __sincosf(0.5f * xv.w, &s3, &c3);
        // p_j = m_a * n_c, j = a*4+c; pairs over c: (n0,n1) and (n2,n3)
        const float m[4] = {c0 * c1, c0 * s1, s0 * c1, s0 * s1};
        const unsigned long long n01 = pack2(c2 * c3, c2 * s3);
        const unsigned long long n23 = pack2(s2 * c3, s2 * s3);
#pragma unroll
        for (int a = 0; a < 4; ++a) {
            const unsigned long long md = pack2(m[a], m[a]);
            pp[e][a * 2 + 0] = mul2(md, n01);
            pp[e][a * 2 + 1] = mul2(md, n23);
        }
    }

    float z0[EPT], z1[EPT], z2[EPT], z3[EPT];
#pragma unroll
    for (int e = 0; e < EPT; ++e) { z0[e] = 0.f; z1[e] = 0.f; z2[e] = 0.f; z3[e] = 0.f; }

#pragma unroll
    for (int k = 0; k < DIM; ++k) {
        // real row: 4 x LDS.128 (broadcast), 8 b64 j-pairs
        const ulonglong2 r0 = sU[k][0], r1 = sU[k][1], r2 = sU[k][2], r3 = sU[k][3];
        unsigned long long aR[EPT];
#pragma unroll
        for (int e = 0; e < EPT; ++e) {
            unsigned long long a = mul2(r0.x, pp[e][0]);
            a = fma2(r0.y, pp[e][1], a);
            a = fma2(r1.x, pp[e][2], a);
            a = fma2(r1.y, pp[e][3], a);
            a = fma2(r2.x, pp[e][4], a);
            a = fma2(r2.y, pp[e][5], a);
            a = fma2(r3.x, pp[e][6], a);
            a = fma2(r3.y, pp[e][7], a);
            aR[e] = a;
        }
        // imaginary row
        const ulonglong2 i0 = sU[k][4], i1 = sU[k][5], i2 = sU[k][6], i3 = sU[k][7];
#pragma unroll
        for (int e = 0; e < EPT; ++e) {
            unsigned long long a = mul2(i0.x, pp[e][0]);
            a = fma2(i0.y, pp[e][1], a);
            a = fma2(i1.x, pp[e][2], a);
            a = fma2(i1.y, pp[e][3], a);
            a = fma2(i2.x, pp[e][4], a);
            a = fma2(i2.y, pp[e][5], a);
            a = fma2(i3.x, pp[e][6], a);
            a = fma2(i3.y, pp[e][7], a);
            // pr = |amp_k|^2 = (lo+hi(aR))^2 + (lo+hi(aI))^2
            float rl, rh, il, ih;
            unpack2(aR[e], rl, rh);   // mov.b64 {}, reg: free
            unpack2(a, il, ih);
            const float re = rl + rh, im = il + ih;
            const float pr = fmaf(im, im, re * re);
            // wire w <-> bit (3-w) of k; signs compile-time
            if (k & 8) z0[e] -= pr; else z0[e] += pr;
            if (k & 4) z1[e] -= pr; else z1[e] += pr;
            if (k & 2) z2[e] -= pr; else z2[e] += pr;
            if (k & 1) z3[e] -= pr; else z3[e] += pr;
        }
    }

#pragma unroll
    for (int e = 0; e < EPT; ++e) {
        if (!valid[e]) continue;
        reinterpret_cast<float4*>(out)[base + e * TPB] =
            make_float4(z0[e], z1[e], z2[e], z3[e]);
    }
}

// ---------------------------------------------------------------------------
extern "C" void kernel_launch(void* const* d_in, const int* in_sizes, int n_in,
                              void* d_out, int out_size) {
    int ix = 0, iw = 1;
    if (n_in >= 2 && in_sizes[0] <= in_sizes[1]) { ix = 1; iw = 0; }
    const float* x = (const float*)d_in[ix];
    const float* w = (const float*)d_in[iw];
    float* out = (float*)d_out;
    const int B = in_sizes[ix] / 4;

    const int per_block = TPB * EPT;
    const int grid = (B + per_block - 1) / per_block;
    vqc_fused_kernel<<<grid, TPB>>>(x, w, out, B);
}